// round 13
// baseline (speedup 1.0000x reference)
#include <cuda_runtime.h>

#define IN_DIM 128
#define OUT_DIM 32
#define NMAX 100000
#define FUSE_BLOCKS 1024

__device__ float g_z[NMAX * OUT_DIM];      // z = h @ W_fc
__device__ float g_el[NMAX];               // z @ a_l
__device__ float g_er[NMAX];               // z @ a_r
__device__ float g_esum[NMAX];             // sum exp(e) per dst
__device__ float g_hacc[NMAX * OUT_DIM];   // edge accumulation (unnormalized)
__device__ float g_stats[2 * OUT_DIM];     // channel sum, sumsq
__device__ unsigned int g_bar_arrive;      // software grid barrier (zero-init)
__device__ unsigned int g_bar_depart;

__device__ __forceinline__ void red_add_v4(float* addr, float4 v) {
    asm volatile("red.global.add.v4.f32 [%0], {%1,%2,%3,%4};"
                 :: "l"(addr), "f"(v.x), "f"(v.y), "f"(v.z), "f"(v.w)
                 : "memory");
}

// ---------------------------------------------------------------------------
// K1: integrated zeroing + z = h @ W_fc ; el/er. (R12 form — at FFMA floor)
// ---------------------------------------------------------------------------
__global__ void __launch_bounds__(256) k_gemm(
    const float* __restrict__ h, const float* __restrict__ Wfc,
    const float* __restrict__ Wa, int n)
{
    __shared__ float Ws[IN_DIM * OUT_DIM];
    __shared__ float Was[2 * OUT_DIM];

    const int tid = blockIdx.x * blockDim.x + threadIdx.x;
    const int gs  = gridDim.x * blockDim.x;

    {
        float4 z4 = make_float4(0.f, 0.f, 0.f, 0.f);
        float4* hacc4 = reinterpret_cast<float4*>(g_hacc);
        const int total4 = n * (OUT_DIM / 4);
        for (int i = tid; i < total4; i += gs) hacc4[i] = z4;
        for (int i = tid; i < n; i += gs) g_esum[i] = 0.0f;
        if (tid < 2 * OUT_DIM) g_stats[tid] = 0.0f;
    }

    for (int i = threadIdx.x; i < IN_DIM * OUT_DIM; i += blockDim.x)
        Ws[i] = Wfc[i];
    if (threadIdx.x < 2 * OUT_DIM) Was[threadIdx.x] = Wa[threadIdx.x];
    __syncthreads();

    const int lane = threadIdx.x & 31;
    const int gw   = tid >> 5;
    const int nw   = gs >> 5;

    for (int base = gw * 32; base < n; base += nw * 32) {
        const int node = base + lane;
        const bool valid = node < n;
        const float4* hrow = reinterpret_cast<const float4*>(h)
                           + (size_t)(valid ? node : 0) * (IN_DIM / 4);

        float acc[OUT_DIM];
        #pragma unroll
        for (int c = 0; c < OUT_DIM; c++) acc[c] = 0.0f;

        #pragma unroll 4
        for (int k4 = 0; k4 < IN_DIM / 4; k4++) {
            const float4 hv = __ldg(hrow + k4);
            #pragma unroll
            for (int c4 = 0; c4 < 8; c4++) {
                const float4 wa = *reinterpret_cast<const float4*>(&Ws[(k4 * 4 + 0) * 32 + c4 * 4]);
                const float4 wb = *reinterpret_cast<const float4*>(&Ws[(k4 * 4 + 1) * 32 + c4 * 4]);
                const float4 wc = *reinterpret_cast<const float4*>(&Ws[(k4 * 4 + 2) * 32 + c4 * 4]);
                const float4 wd = *reinterpret_cast<const float4*>(&Ws[(k4 * 4 + 3) * 32 + c4 * 4]);
                acc[c4 * 4 + 0] = fmaf(hv.x, wa.x, acc[c4 * 4 + 0]);
                acc[c4 * 4 + 0] = fmaf(hv.y, wb.x, acc[c4 * 4 + 0]);
                acc[c4 * 4 + 0] = fmaf(hv.z, wc.x, acc[c4 * 4 + 0]);
                acc[c4 * 4 + 0] = fmaf(hv.w, wd.x, acc[c4 * 4 + 0]);
                acc[c4 * 4 + 1] = fmaf(hv.x, wa.y, acc[c4 * 4 + 1]);
                acc[c4 * 4 + 1] = fmaf(hv.y, wb.y, acc[c4 * 4 + 1]);
                acc[c4 * 4 + 1] = fmaf(hv.z, wc.y, acc[c4 * 4 + 1]);
                acc[c4 * 4 + 1] = fmaf(hv.w, wd.y, acc[c4 * 4 + 1]);
                acc[c4 * 4 + 2] = fmaf(hv.x, wa.z, acc[c4 * 4 + 2]);
                acc[c4 * 4 + 2] = fmaf(hv.y, wb.z, acc[c4 * 4 + 2]);
                acc[c4 * 4 + 2] = fmaf(hv.z, wc.z, acc[c4 * 4 + 2]);
                acc[c4 * 4 + 2] = fmaf(hv.w, wd.z, acc[c4 * 4 + 2]);
                acc[c4 * 4 + 3] = fmaf(hv.x, wa.w, acc[c4 * 4 + 3]);
                acc[c4 * 4 + 3] = fmaf(hv.y, wb.w, acc[c4 * 4 + 3]);
                acc[c4 * 4 + 3] = fmaf(hv.z, wc.w, acc[c4 * 4 + 3]);
                acc[c4 * 4 + 3] = fmaf(hv.w, wd.w, acc[c4 * 4 + 3]);
            }
        }

        float el = 0.f, er = 0.f;
        #pragma unroll
        for (int c4 = 0; c4 < 8; c4++) {
            const float4 a = *reinterpret_cast<const float4*>(&Was[c4 * 4]);
            const float4 b = *reinterpret_cast<const float4*>(&Was[OUT_DIM + c4 * 4]);
            el = fmaf(acc[c4 * 4 + 0], a.x, el);
            el = fmaf(acc[c4 * 4 + 1], a.y, el);
            el = fmaf(acc[c4 * 4 + 2], a.z, el);
            el = fmaf(acc[c4 * 4 + 3], a.w, el);
            er = fmaf(acc[c4 * 4 + 0], b.x, er);
            er = fmaf(acc[c4 * 4 + 1], b.y, er);
            er = fmaf(acc[c4 * 4 + 2], b.z, er);
            er = fmaf(acc[c4 * 4 + 3], b.w, er);
        }

        if (valid) {
            float4* zrow = reinterpret_cast<float4*>(g_z) + (size_t)node * (OUT_DIM / 4);
            #pragma unroll
            for (int c4 = 0; c4 < 8; c4++)
                zrow[c4] = make_float4(acc[c4 * 4 + 0], acc[c4 * 4 + 1],
                                       acc[c4 * 4 + 2], acc[c4 * 4 + 3]);
            g_el[node] = el;
            g_er[node] = er;
        }
    }
}

// ---------------------------------------------------------------------------
// K2: edge pass (unchanged best form).
// ---------------------------------------------------------------------------
__global__ void __launch_bounds__(256) k_edges(
    const int* __restrict__ src, const int* __restrict__ dst, int nedges)
{
    const int lane = threadIdx.x & 31;
    const int sub  = lane >> 3;
    const int q    = lane & 7;
    const int gw   = (blockIdx.x * blockDim.x + threadIdx.x) >> 5;
    const int nw   = (gridDim.x * blockDim.x) >> 5;

    for (int base = gw * 8; base < nedges; base += nw * 8) {
        const int e0 = base + sub;
        const int e1 = base + 4 + sub;
        const bool v0 = e0 < nedges;
        const bool v1 = e1 < nedges;

        int s0 = 0, d0 = 0, s1 = 0, d1 = 0;
        if (v0) { s0 = __ldg(&src[e0]); d0 = __ldg(&dst[e0]); }
        if (v1) { s1 = __ldg(&src[e1]); d1 = __ldg(&dst[e1]); }

        float ee0 = 0.f, ee1 = 0.f;
        if (v0) ee0 = __ldg(&g_el[s0]) + __ldg(&g_er[d0]);
        if (v1) ee1 = __ldg(&g_el[s1]) + __ldg(&g_er[d1]);
        ee0 = (ee0 >= 0.0f) ? ee0 : 0.01f * ee0;
        ee1 = (ee1 >= 0.0f) ? ee1 : 0.01f * ee1;
        const float p0 = __expf(ee0);
        const float p1 = __expf(ee1);

        float4 zv0, zv1;
        if (v0) zv0 = __ldg(reinterpret_cast<const float4*>(g_z + s0 * OUT_DIM) + q);
        if (v1) zv1 = __ldg(reinterpret_cast<const float4*>(g_z + s1 * OUT_DIM) + q);

        if (v0) {
            if (q == 0) atomicAdd(&g_esum[d0], p0);
            red_add_v4(g_hacc + d0 * OUT_DIM + q * 4,
                       make_float4(p0 * zv0.x, p0 * zv0.y, p0 * zv0.z, p0 * zv0.w));
        }
        if (v1) {
            if (q == 0) atomicAdd(&g_esum[d1], p1);
            red_add_v4(g_hacc + d1 * OUT_DIM + q * 4,
                       make_float4(p1 * zv1.x, p1 * zv1.y, p1 * zv1.z, p1 * zv1.w));
        }
    }
}

// ---------------------------------------------------------------------------
// K3: fused BN-stats + affine + ELU. Persistent grid with software barrier.
// Phase 1: per-channel sum/sumsq of v = hacc*inv (no writeback).
// Barrier. Phase 2: recompute v (hacc L2-hot), affine+ELU, write out.
// Barrier counters self-reset for graph replay.
// ---------------------------------------------------------------------------
__global__ void __launch_bounds__(256) k_fused(float* __restrict__ out,
                                               const float* __restrict__ gamma,
                                               const float* __restrict__ beta, int n)
{
    __shared__ float redbuf[2][8][32];
    __shared__ float sc_s[OUT_DIM], sh_s[OUT_DIM];
    const int lane = threadIdx.x & 31;
    const int wid  = threadIdx.x >> 5;
    const int gw   = (blockIdx.x * blockDim.x + threadIdx.x) >> 5;
    const int nw   = (gridDim.x * blockDim.x) >> 5;

    // ---- phase 1: stats ----
    float s = 0.f, sq = 0.f;
    for (int nd = gw; nd < n; nd += 2 * nw) {
        const int n0 = nd;
        const int n1 = nd + nw;
        const bool v1 = n1 < n;
        const float a0 = g_hacc[n0 * OUT_DIM + lane];
        const float a1 = v1 ? g_hacc[n1 * OUT_DIM + lane] : 0.0f;
        float inv0 = 0.f, inv1 = 0.f;
        if (lane == 0) {
            const float e0 = g_esum[n0];
            const float e1 = v1 ? g_esum[n1] : 0.0f;
            inv0 = (e0 > 0.0f) ? __frcp_rn(e0) : 0.0f;
            inv1 = (e1 > 0.0f) ? __frcp_rn(e1) : 0.0f;
        }
        inv0 = __shfl_sync(0xffffffffu, inv0, 0);
        inv1 = __shfl_sync(0xffffffffu, inv1, 0);
        const float x0 = a0 * inv0;
        const float x1 = a1 * inv1;
        s += x0 + x1;
        sq = fmaf(x0, x0, sq);
        sq = fmaf(x1, x1, sq);
    }
    redbuf[0][wid][lane] = s;
    redbuf[1][wid][lane] = sq;
    __syncthreads();
    if (wid == 0) {
        float a = 0.f, b = 0.f;
        #pragma unroll
        for (int w = 0; w < 8; w++) { a += redbuf[0][w][lane]; b += redbuf[1][w][lane]; }
        atomicAdd(&g_stats[lane], a);
        atomicAdd(&g_stats[OUT_DIM + lane], b);
    }

    // ---- software grid barrier (arrive/depart, self-resetting) ----
    __syncthreads();
    if (threadIdx.x == 0) {
        __threadfence();
        atomicAdd(&g_bar_arrive, 1u);
        while (*(volatile unsigned int*)&g_bar_arrive < (unsigned)gridDim.x) { }
        __threadfence();
        const unsigned d = atomicAdd(&g_bar_depart, 1u);
        if (d == (unsigned)gridDim.x - 1u) {   // last block out resets for next replay
            g_bar_arrive = 0u;
            __threadfence();
            g_bar_depart = 0u;
        }
    }
    __syncthreads();

    // ---- affine fold (per block, from global stats) ----
    if (threadIdx.x < OUT_DIM) {
        const int t = threadIdx.x;
        const float inv_n = 1.0f / (float)n;
        const float mean = g_stats[t] * inv_n;
        const float var  = g_stats[OUT_DIM + t] * inv_n - mean * mean;
        const float sc   = gamma[t] * rsqrtf(var + 1e-5f);
        sc_s[t] = sc;
        sh_s[t] = beta[t] - mean * sc;
    }
    __syncthreads();

    // ---- phase 2: normalize + affine + ELU, single out write ----
    const float sc = sc_s[lane];
    const float sh = sh_s[lane];
    for (int nd = gw; nd < n; nd += 2 * nw) {
        const int n0 = nd;
        const int n1 = nd + nw;
        const bool v1 = n1 < n;
        const float a0 = g_hacc[n0 * OUT_DIM + lane];
        const float a1 = v1 ? g_hacc[n1 * OUT_DIM + lane] : 0.0f;
        float inv0 = 0.f, inv1 = 0.f;
        if (lane == 0) {
            const float e0 = g_esum[n0];
            const float e1 = v1 ? g_esum[n1] : 0.0f;
            inv0 = (e0 > 0.0f) ? __frcp_rn(e0) : 0.0f;
            inv1 = (e1 > 0.0f) ? __frcp_rn(e1) : 0.0f;
        }
        inv0 = __shfl_sync(0xffffffffu, inv0, 0);
        inv1 = __shfl_sync(0xffffffffu, inv1, 0);
        float x0 = fmaf(a0 * inv0, sc, sh);
        x0 = (x0 > 0.0f) ? x0 : expm1f(x0);
        out[n0 * OUT_DIM + lane] = x0;
        if (v1) {
            float x1 = fmaf(a1 * inv1, sc, sh);
            x1 = (x1 > 0.0f) ? x1 : expm1f(x1);
            out[n1 * OUT_DIM + lane] = x1;
        }
    }
}

// ---------------------------------------------------------------------------
extern "C" void kernel_launch(void* const* d_in, const int* in_sizes, int n_in,
                              void* d_out, int out_size)
{
    const float* h     = (const float*)d_in[0];
    const float* Wfc   = (const float*)d_in[1];
    const float* Wa    = (const float*)d_in[2];
    const float* gamma = (const float*)d_in[3];
    const float* beta  = (const float*)d_in[4];
    const int*   src   = (const int*)d_in[5];
    const int*   dst   = (const int*)d_in[6];

    const int n      = in_sizes[0] / IN_DIM;   // 100000
    const int nedges = in_sizes[5];            // 1600000
    float* out = (float*)d_out;

    k_gemm <<<400, 256>>>(h, Wfc, Wa, n);
    k_edges<<<4096, 256>>>(src, dst, nedges);
    k_fused<<<FUSE_BLOCKS, 256>>>(out, gamma, beta, n);
}

// round 16
// speedup vs baseline: 1.0613x; 1.0613x over previous
#include <cuda_runtime.h>

#define IN_DIM 128
#define OUT_DIM 32
#define NMAX 100000
#define GW 4   // warps per gemm block

__device__ float g_z[NMAX * OUT_DIM];      // z = h @ W_fc
__device__ float g_el[NMAX];               // z @ a_l
__device__ float g_er[NMAX];               // z @ a_r
__device__ float g_esum[NMAX];             // sum exp(e) per dst
__device__ float g_hacc[NMAX * OUT_DIM];   // edge accumulation, then h_out
__device__ float g_stats[2 * OUT_DIM];     // channel sum, sumsq

__device__ __forceinline__ void red_add_v4(float* addr, float4 v) {
    asm volatile("red.global.add.v4.f32 [%0], {%1,%2,%3,%4};"
                 :: "l"(addr), "f"(v.x), "f"(v.y), "f"(v.z), "f"(v.w)
                 : "memory");
}

// ---------------------------------------------------------------------------
// K1: integrated zeroing + z = h @ W_fc ; el/er.
// 128-thread blocks (4 warps). Warp-per-8-nodes: coalesced LDG.128 staging of
// h rows into per-warp smem, lane = channel compute, padded conflict-free W.
// Static smem: 16.9K (Wt4) + 16K (hstage) + 0.25K = ~33.5 KB.
// ---------------------------------------------------------------------------
__global__ void __launch_bounds__(128) k_gemm(
    const float* __restrict__ h, const float* __restrict__ Wfc,
    const float* __restrict__ Wa, int n)
{
    __shared__ float4 Wt4[OUT_DIM][33];        // [channel][k4], pad -> staggered banks
    __shared__ float4 hstage[GW][8 * 32];      // per-warp: 8 rows x 32 float4 = 4 KB
    __shared__ float  Was[2 * OUT_DIM];

    const int tid = blockIdx.x * blockDim.x + threadIdx.x;
    const int gs  = gridDim.x * blockDim.x;

    {   // zero accumulators (store pipe idle during FMA-heavy GEMM)
        float4 z4 = make_float4(0.f, 0.f, 0.f, 0.f);
        float4* hacc4 = reinterpret_cast<float4*>(g_hacc);
        const int total4 = n * (OUT_DIM / 4);
        for (int i = tid; i < total4; i += gs) hacc4[i] = z4;
        for (int i = tid; i < n; i += gs) g_esum[i] = 0.0f;
        if (tid < 2 * OUT_DIM) g_stats[tid] = 0.0f;
    }

    // Wt4[c][k4] = { W[4k4+0][c], W[4k4+1][c], W[4k4+2][c], W[4k4+3][c] }
    for (int i = threadIdx.x; i < IN_DIM * OUT_DIM; i += blockDim.x) {
        const int k = i >> 5;          // 0..127
        const int c = i & 31;          // 0..31
        reinterpret_cast<float*>(&Wt4[c][k >> 2])[k & 3] = Wfc[i];
    }
    if (threadIdx.x < 2 * OUT_DIM) Was[threadIdx.x] = Wa[threadIdx.x];
    __syncthreads();

    const int lane = threadIdx.x & 31;
    const int wid  = threadIdx.x >> 5;
    const int gw   = tid >> 5;
    const int nw   = gs >> 5;

    const float al = Was[lane];
    const float ar = Was[OUT_DIM + lane];
    float4* hsw = hstage[wid];
    const float4* wrow = Wt4[lane];

    for (int base = gw * 8; base < n; base += nw * 8) {
        const int nrem = n - base;
        const int cnt = (nrem < 8) ? nrem : 8;

        // stage up to 8 h rows, fully coalesced (lane = float4 column)
        #pragma unroll
        for (int r = 0; r < 8; r++) {
            if (r < cnt)
                hsw[r * 32 + lane] =
                    reinterpret_cast<const float4*>(h)[(size_t)(base + r) * 32 + lane];
        }
        __syncwarp();

        float acc[8];
        #pragma unroll
        for (int r = 0; r < 8; r++) acc[r] = 0.0f;

        #pragma unroll 4
        for (int k4 = 0; k4 < 32; k4++) {
            const float4 w = wrow[k4];             // per-lane LDS.128, staggered banks
            #pragma unroll
            for (int r = 0; r < 8; r++) {
                const float4 hv = hsw[r * 32 + k4]; // broadcast LDS.128
                acc[r] = fmaf(hv.x, w.x, acc[r]);
                acc[r] = fmaf(hv.y, w.y, acc[r]);
                acc[r] = fmaf(hv.z, w.z, acc[r]);
                acc[r] = fmaf(hv.w, w.w, acc[r]);
            }
        }

        // z stores (coalesced per row) + el/er shfl reductions
        #pragma unroll
        for (int r = 0; r < 8; r++) {
            if (r >= cnt) break;
            const int node = base + r;
            g_z[(size_t)node * OUT_DIM + lane] = acc[r];
            float vl = acc[r] * al;
            float vr = acc[r] * ar;
            #pragma unroll
            for (int off = 16; off; off >>= 1) {
                vl += __shfl_xor_sync(0xffffffffu, vl, off);
                vr += __shfl_xor_sync(0xffffffffu, vr, off);
            }
            if (lane == 0) { g_el[node] = vl; g_er[node] = vr; }
        }
        __syncwarp();
    }
}

// ---------------------------------------------------------------------------
// K2: edge pass (unchanged best form): 8 edges/warp, 8 lanes/edge,
// float4 gather + v4 fp32 REDs. Unnormalized softmax accumulation.
// ---------------------------------------------------------------------------
__global__ void __launch_bounds__(256) k_edges(
    const int* __restrict__ src, const int* __restrict__ dst, int nedges)
{
    const int lane = threadIdx.x & 31;
    const int sub  = lane >> 3;
    const int q    = lane & 7;
    const int gw   = (blockIdx.x * blockDim.x + threadIdx.x) >> 5;
    const int nw   = (gridDim.x * blockDim.x) >> 5;

    for (int base = gw * 8; base < nedges; base += nw * 8) {
        const int e0 = base + sub;
        const int e1 = base + 4 + sub;
        const bool v0 = e0 < nedges;
        const bool v1 = e1 < nedges;

        int s0 = 0, d0 = 0, s1 = 0, d1 = 0;
        if (v0) { s0 = __ldg(&src[e0]); d0 = __ldg(&dst[e0]); }
        if (v1) { s1 = __ldg(&src[e1]); d1 = __ldg(&dst[e1]); }

        float ee0 = 0.f, ee1 = 0.f;
        if (v0) ee0 = __ldg(&g_el[s0]) + __ldg(&g_er[d0]);
        if (v1) ee1 = __ldg(&g_el[s1]) + __ldg(&g_er[d1]);
        ee0 = (ee0 >= 0.0f) ? ee0 : 0.01f * ee0;
        ee1 = (ee1 >= 0.0f) ? ee1 : 0.01f * ee1;
        const float p0 = __expf(ee0);
        const float p1 = __expf(ee1);

        float4 zv0, zv1;
        if (v0) zv0 = __ldg(reinterpret_cast<const float4*>(g_z + s0 * OUT_DIM) + q);
        if (v1) zv1 = __ldg(reinterpret_cast<const float4*>(g_z + s1 * OUT_DIM) + q);

        if (v0) {
            if (q == 0) atomicAdd(&g_esum[d0], p0);
            red_add_v4(g_hacc + d0 * OUT_DIM + q * 4,
                       make_float4(p0 * zv0.x, p0 * zv0.y, p0 * zv0.z, p0 * zv0.w));
        }
        if (v1) {
            if (q == 0) atomicAdd(&g_esum[d1], p1);
            red_add_v4(g_hacc + d1 * OUT_DIM + q * 4,
                       make_float4(p1 * zv1.x, p1 * zv1.y, p1 * zv1.z, p1 * zv1.w));
        }
    }
}

// ---------------------------------------------------------------------------
// K3: normalize in place (hacc <- hacc/esum) + BN stats. 2-node ILP chains.
// ---------------------------------------------------------------------------
__global__ void __launch_bounds__(256) k_stats(int n)
{
    __shared__ float redbuf[2][8][32];
    const int lane = threadIdx.x & 31;
    const int wid  = threadIdx.x >> 5;
    const int gw   = (blockIdx.x * blockDim.x + threadIdx.x) >> 5;
    const int nw   = (gridDim.x * blockDim.x) >> 5;

    float s = 0.f, sq = 0.f;
    for (int nd = gw; nd < n; nd += 2 * nw) {
        const int n0 = nd;
        const int n1 = nd + nw;
        const bool v1 = n1 < n;
        const float a0 = g_hacc[n0 * OUT_DIM + lane];
        const float a1 = v1 ? g_hacc[n1 * OUT_DIM + lane] : 0.0f;
        float inv0 = 0.f, inv1 = 0.f;
        if (lane == 0) {
            const float e0 = g_esum[n0];
            const float e1 = v1 ? g_esum[n1] : 0.0f;
            inv0 = (e0 > 0.0f) ? __frcp_rn(e0) : 0.0f;
            inv1 = (e1 > 0.0f) ? __frcp_rn(e1) : 0.0f;
        }
        inv0 = __shfl_sync(0xffffffffu, inv0, 0);
        inv1 = __shfl_sync(0xffffffffu, inv1, 0);
        const float x0 = a0 * inv0;
        const float x1 = a1 * inv1;
        g_hacc[n0 * OUT_DIM + lane] = x0;              // h_out, pre-BN
        if (v1) g_hacc[n1 * OUT_DIM + lane] = x1;
        s += x0 + x1;
        sq = fmaf(x0, x0, sq);
        sq = fmaf(x1, x1, sq);
    }
    redbuf[0][wid][lane] = s;
    redbuf[1][wid][lane] = sq;
    __syncthreads();
    if (wid == 0) {
        float a = 0.f, b = 0.f;
        #pragma unroll
        for (int w = 0; w < 8; w++) { a += redbuf[0][w][lane]; b += redbuf[1][w][lane]; }
        atomicAdd(&g_stats[lane], a);
        atomicAdd(&g_stats[OUT_DIM + lane], b);
    }
}

// ---------------------------------------------------------------------------
// K4: BN affine + ELU — pure float4 map, single read + single write.
// ---------------------------------------------------------------------------
__global__ void __launch_bounds__(256) k_elu(float* __restrict__ out,
                                             const float* __restrict__ gamma,
                                             const float* __restrict__ beta, int n)
{
    __shared__ float sc_s[OUT_DIM], sh_s[OUT_DIM];
    if (threadIdx.x < OUT_DIM) {
        const int t = threadIdx.x;
        const float inv_n = 1.0f / (float)n;
        const float mean = g_stats[t] * inv_n;
        const float var  = g_stats[OUT_DIM + t] * inv_n - mean * mean;
        const float sc   = gamma[t] * rsqrtf(var + 1e-5f);
        sc_s[t] = sc;
        sh_s[t] = beta[t] - mean * sc;
    }
    __syncthreads();

    const int q = threadIdx.x & 7;
    const float4 sc = reinterpret_cast<const float4*>(sc_s)[q];
    const float4 sh = reinterpret_cast<const float4*>(sh_s)[q];
    const int total4 = n * (OUT_DIM / 4);
    const int stride = gridDim.x * blockDim.x;
    const float4* hacc4 = reinterpret_cast<const float4*>(g_hacc);
    float4* out4 = reinterpret_cast<float4*>(out);

    for (int i = blockIdx.x * blockDim.x + threadIdx.x; i < total4; i += stride) {
        float4 v = hacc4[i];
        v.x = fmaf(v.x, sc.x, sh.x);
        v.y = fmaf(v.y, sc.y, sh.y);
        v.z = fmaf(v.z, sc.z, sh.z);
        v.w = fmaf(v.w, sc.w, sh.w);
        v.x = (v.x > 0.f) ? v.x : expm1f(v.x);
        v.y = (v.y > 0.f) ? v.y : expm1f(v.y);
        v.z = (v.z > 0.f) ? v.z : expm1f(v.z);
        v.w = (v.w > 0.f) ? v.w : expm1f(v.w);
        out4[i] = v;
    }
}

// ---------------------------------------------------------------------------
extern "C" void kernel_launch(void* const* d_in, const int* in_sizes, int n_in,
                              void* d_out, int out_size)
{
    const float* h     = (const float*)d_in[0];
    const float* Wfc   = (const float*)d_in[1];
    const float* Wa    = (const float*)d_in[2];
    const float* gamma = (const float*)d_in[3];
    const float* beta  = (const float*)d_in[4];
    const int*   src   = (const int*)d_in[5];
    const int*   dst   = (const int*)d_in[6];

    const int n      = in_sizes[0] / IN_DIM;   // 100000
    const int nedges = in_sizes[5];            // 1600000
    float* out = (float*)d_out;

    k_gemm <<<1184, 128>>>(h, Wfc, Wa, n);     // 4736 warps, ~6 blocks/SM (smem-limited)
    k_edges<<<4096, 256>>>(src, dst, nedges);
    k_stats<<<1024, 256>>>(n);
    k_elu  <<<1024, 256>>>(out, gamma, beta, n);
}